// round 16
// baseline (speedup 1.0000x reference)
#include <cuda_runtime.h>
#include <cstdint>

// LatentTexture: quantize-then-bilinear-sample two latent textures.
//   hi: 12 ch, 2048x2048, 8-bit quant (qmax=255)
//   lo:  4 ch,  512x512,  4-bit quant (qmax=15)
// out[b,0:12]=hi, out[b,12:16]=lo. fp32.
//
// R16 (on top of the R15 WIN):
//   - scatter also computes the LO result per sample (lo is L2-resident;
//     its loads overlap the 318-cyc binning atomics) and writes out[...,12:16].
//   - gather: 3 lanes per slot (j=0..2 hi channel groups only).
//   - overflow records: hi only.
// Replay safety: bin fill counts are input-deterministic; slots < count are
// rewritten every replay, slots >= count keep pad=0 from load-time zero-init.
// Cursors / overflow counter are re-zeroed inside gather (which never reads
// them), ordered after scatter by launch order.

#define NSAMP 131072
#define BLK 256
#define NBINS 16384              // 128x128 tiles of 16x16 hi texels
#define CAP 16                   // slots per bin (mean load 8)
#define NSLOTS (NBINS * CAP)     // 262144
#define OCAP 8192                // overflow capacity (expected ~200 used)

#define OV_BLOCKS 16
#define SLOT_BLOCKS (NSLOTS * 3 / BLK)        // 3072
#define GATHER_BLOCKS (OV_BLOCKS + SLOT_BLOCKS)

__device__ int    g_cursor[NBINS];   // zeroed at load; gather re-zeroes
__device__ int    g_over_cnt;        // zeroed at load; gather re-zeroes
__device__ float4 g_slots[NSLOTS];   // (u, v, idx_bits, valid) pad=0 invalid
__device__ float4 g_over[OCAP];

// ---------------------------------------------------------------- helpers
__device__ __forceinline__ float qlevel(float x, float qmax) {
    float xc = fminf(fmaxf(x, 0.0f), 1.0f);
    return rintf(__fmul_rn(xc, qmax));
}

__device__ __forceinline__ uint32_t spread8(uint32_t x) {
    x &= 0xFFu;
    x = (x | (x << 4)) & 0x0F0Fu;
    x = (x | (x << 2)) & 0x3333u;
    x = (x | (x << 1)) & 0x5555u;
    return x;
}

__device__ __forceinline__ int sample_key(float u, float v) {
    float gx = __fadd_rn(__fmul_rn(u, 2.0f), -1.0f);
    float gy = __fadd_rn(__fmul_rn(v, 2.0f), -1.0f);
    float ix = __fmul_rn(__fmul_rn(__fadd_rn(gx, 1.0f), 0.5f), 2047.0f);
    float iy = __fmul_rn(__fmul_rn(__fadd_rn(gy, 1.0f), 0.5f), 2047.0f);
    int tx = min(max((int)floorf(ix), 0), 2047) >> 4;   // 0..127
    int ty = min(max((int)floorf(iy), 0), 2047) >> 4;   // 0..127
    return (int)((spread8((uint32_t)ty) << 1) | spread8((uint32_t)tx));
}

// ---------------------------------------------------------------- sampling
template <int HW>
__device__ __forceinline__ void sample4(const float* __restrict__ tex,
                                        float u, float v,
                                        float qmax, float invq,
                                        float* __restrict__ res) {
    float gx = __fadd_rn(__fmul_rn(u, 2.0f), -1.0f);
    float gy = __fadd_rn(__fmul_rn(v, 2.0f), -1.0f);
    float ix = __fmul_rn(__fmul_rn(__fadd_rn(gx, 1.0f), 0.5f), (float)(HW - 1));
    float iy = __fmul_rn(__fmul_rn(__fadd_rn(gy, 1.0f), 0.5f), (float)(HW - 1));

    float ix0f = floorf(ix);
    float iy0f = floorf(iy);
    float wx = __fadd_rn(ix, -ix0f);
    float wy = __fadd_rn(iy, -iy0f);

    int ix0 = min(max((int)ix0f, 0), HW - 1);
    int iy0 = min(max((int)iy0f, 0), HW - 1);
    int ix1 = min(ix0 + 1, HW - 1);
    int iy1 = min(iy0 + 1, HW - 1);

    float w00 = (1.0f - wy) * (1.0f - wx);
    float w01 = (1.0f - wy) * wx;
    float w10 = wy * (1.0f - wx);
    float w11 = wy * wx;

    size_t r0 = (size_t)iy0 * HW;
    size_t r1 = (size_t)iy1 * HW;
    size_t o00 = r0 + ix0, o01 = r0 + ix1;
    size_t o10 = r1 + ix0, o11 = r1 + ix1;

    const size_t plane = (size_t)HW * HW;

    float t00[4], t01[4], t10[4], t11[4];
#pragma unroll
    for (int c = 0; c < 4; ++c) {
        const float* p = tex + (size_t)c * plane;
        t00[c] = __ldg(p + o00);
        t01[c] = __ldg(p + o01);
        t10[c] = __ldg(p + o10);
        t11[c] = __ldg(p + o11);
    }
#pragma unroll
    for (int c = 0; c < 4; ++c) {
        float acc = qlevel(t00[c], qmax) * w00
                  + qlevel(t01[c], qmax) * w01
                  + qlevel(t10[c], qmax) * w10
                  + qlevel(t11[c], qmax) * w11;
        res[c] = acc * invq;
    }
}

// ---------------------------------------------------------------- scatter (+lo)
__global__ void __launch_bounds__(BLK)
scatter_kernel(const float* __restrict__ uv,
               const float* __restrict__ lo,
               float* __restrict__ out) {
    int t = blockIdx.x * BLK + threadIdx.x;          // t in [0, NSAMP/4)
    const float4* uv4 = reinterpret_cast<const float4*>(uv);
    float4 a = __ldg(uv4 + 2 * t);
    float4 b = __ldg(uv4 + 2 * t + 1);

    float us[4] = {a.x, a.z, b.x, b.z};
    float vs[4] = {a.y, a.w, b.y, b.w};
    int key[4], pos[4];
#pragma unroll
    for (int k = 0; k < 4; ++k)
        key[k] = sample_key(us[k], vs[k]);
#pragma unroll
    for (int k = 0; k < 4; ++k)                      // 4 independent atomics
        pos[k] = atomicAdd(&g_cursor[key[k]], 1);
#pragma unroll
    for (int k = 0; k < 4; ++k) {
        float4 rec = make_float4(us[k], vs[k],
                                 __int_as_float(4 * t + k), 1.0f);
        if (pos[k] < CAP) {
            g_slots[key[k] * CAP + pos[k]] = rec;
        } else {
            int o = atomicAdd(&g_over_cnt, 1);
            if (o < OCAP) g_over[o] = rec;
        }
    }

    // lo gather for the same 4 samples (L2-resident texture; overlaps the
    // atomic/store latency above).
#pragma unroll
    for (int k = 0; k < 4; ++k) {
        float res[4];
        sample4<512>(lo, us[k], vs[k], 15.0f, 1.0f / 15.0f, res);
        reinterpret_cast<float4*>(out)[(size_t)(4 * t + k) * 4 + 3] =
            make_float4(res[0], res[1], res[2], res[3]);
    }
}

// ---------------------------------------------------------------- gather (hi)
__global__ void __launch_bounds__(BLK)
gather_kernel(const float* __restrict__ hi,
              float* __restrict__ out) {
    int b = blockIdx.x;
    int tid = threadIdx.x;
    const size_t plane = (size_t)2048 * 2048;

    if (b < OV_BLOCKS) {
        // ---- cleanup + overflow records (hi channels only) ----
        reinterpret_cast<int4*>(g_cursor)[b * BLK + tid] =
            make_int4(0, 0, 0, 0);                 // 16*256 int4 = all bins
        if (b == 0 && tid == 0) g_over_cnt = 0;

        for (int r = b * BLK + tid; r < OCAP; r += OV_BLOCKS * BLK) {
            float4 rec = __ldg(reinterpret_cast<const float4*>(g_over) + r);
            if (rec.w != 0.0f) {
                int idx = __float_as_int(rec.z);
                float res[4];
#pragma unroll
                for (int j = 0; j < 3; ++j) {
                    sample4<2048>(hi + (size_t)(j * 4) * plane, rec.x, rec.y,
                                  255.0f, 1.0f / 255.0f, res);
                    reinterpret_cast<float4*>(out)[(size_t)idx * 4 + j] =
                        make_float4(res[0], res[1], res[2], res[3]);
                }
            }
        }
        return;
    }

    // ---- 3 lanes per slot ----
    int t = (b - OV_BLOCKS) * BLK + tid;
    int s = t / 3;                                  // slot index
    int j = t - 3 * s;                              // hi channel group 0..2

    float4 rec = __ldg(reinterpret_cast<const float4*>(g_slots) + s);
    if (rec.w == 0.0f) return;                      // empty slot
    int idx = __float_as_int(rec.z);

    float res[4];
    sample4<2048>(hi + (size_t)(j * 4) * plane, rec.x, rec.y,
                  255.0f, 1.0f / 255.0f, res);
    reinterpret_cast<float4*>(out)[(size_t)idx * 4 + j] =
        make_float4(res[0], res[1], res[2], res[3]);
}

// ---------------------------------------------------------------- launch
extern "C" void kernel_launch(void* const* d_in, const int* in_sizes, int n_in,
                              void* d_out, int out_size) {
    const float* uv = (const float*)d_in[0];
    const float* hi = (const float*)d_in[1];
    const float* lo = (const float*)d_in[2];
    float* out = (float*)d_out;

    scatter_kernel<<<NSAMP / 4 / BLK, BLK>>>(uv, lo, out);
    gather_kernel<<<GATHER_BLOCKS, BLK>>>(hi, out);
}

// round 17
// speedup vs baseline: 1.1296x; 1.1296x over previous
#include <cuda_runtime.h>
#include <cstdint>

// LatentTexture: quantize-then-bilinear-sample two latent textures.
//   hi: 12 ch, 2048x2048, 8-bit quant (qmax=255)
//   lo:  4 ch,  512x512,  4-bit quant (qmax=15)
// out[b,0:12]=hi, out[b,12:16]=lo. fp32.
//
// R17 = R15 (best, 41.4us) with the scatter spread over 4x more blocks:
//   scatter: 4 samples/thread, BLK=64 -> 512 blocks. Pure latency kernel
//            (318-cyc atomics); more resident warps shorten the chain-bound
//            region.
//   gather:  QUAD per slot (j=0..2 hi groups, j=3 lo). lo is proven free
//            inside the gather (hides under hi DRAM traffic).
// Replay safety: bin fill counts are input-deterministic; slots < count are
// rewritten every replay, slots >= count keep pad=0 from load-time zero-init.
// Cursors / overflow counter are re-zeroed inside gather (which never reads
// them), ordered after scatter by launch order.

#define NSAMP 131072
#define SCBLK 64                 // scatter block size
#define BLK 256                  // gather block size
#define NBINS 16384              // 128x128 tiles of 16x16 hi texels
#define CAP 16                   // slots per bin (mean load 8)
#define NSLOTS (NBINS * CAP)     // 262144
#define OCAP 8192                // overflow capacity (expected ~200 used)

#define OV_BLOCKS 16
#define SLOT_BLOCKS (NSLOTS * 4 / BLK)        // 4096
#define GATHER_BLOCKS (OV_BLOCKS + SLOT_BLOCKS)

__device__ int    g_cursor[NBINS];   // zeroed at load; gather re-zeroes
__device__ int    g_over_cnt;        // zeroed at load; gather re-zeroes
__device__ float4 g_slots[NSLOTS];   // (u, v, idx_bits, valid) pad=0 invalid
__device__ float4 g_over[OCAP];

// ---------------------------------------------------------------- helpers
__device__ __forceinline__ float qlevel(float x, float qmax) {
    float xc = fminf(fmaxf(x, 0.0f), 1.0f);
    return rintf(__fmul_rn(xc, qmax));
}

__device__ __forceinline__ uint32_t spread8(uint32_t x) {
    x &= 0xFFu;
    x = (x | (x << 4)) & 0x0F0Fu;
    x = (x | (x << 2)) & 0x3333u;
    x = (x | (x << 1)) & 0x5555u;
    return x;
}

__device__ __forceinline__ int sample_key(float u, float v) {
    float gx = __fadd_rn(__fmul_rn(u, 2.0f), -1.0f);
    float gy = __fadd_rn(__fmul_rn(v, 2.0f), -1.0f);
    float ix = __fmul_rn(__fmul_rn(__fadd_rn(gx, 1.0f), 0.5f), 2047.0f);
    float iy = __fmul_rn(__fmul_rn(__fadd_rn(gy, 1.0f), 0.5f), 2047.0f);
    int tx = min(max((int)floorf(ix), 0), 2047) >> 4;   // 0..127
    int ty = min(max((int)floorf(iy), 0), 2047) >> 4;   // 0..127
    return (int)((spread8((uint32_t)ty) << 1) | spread8((uint32_t)tx));
}

// ---------------------------------------------------------------- sampling
template <int HW>
__device__ __forceinline__ void sample4(const float* __restrict__ tex,
                                        float u, float v,
                                        float qmax, float invq,
                                        float* __restrict__ res) {
    float gx = __fadd_rn(__fmul_rn(u, 2.0f), -1.0f);
    float gy = __fadd_rn(__fmul_rn(v, 2.0f), -1.0f);
    float ix = __fmul_rn(__fmul_rn(__fadd_rn(gx, 1.0f), 0.5f), (float)(HW - 1));
    float iy = __fmul_rn(__fmul_rn(__fadd_rn(gy, 1.0f), 0.5f), (float)(HW - 1));

    float ix0f = floorf(ix);
    float iy0f = floorf(iy);
    float wx = __fadd_rn(ix, -ix0f);
    float wy = __fadd_rn(iy, -iy0f);

    int ix0 = min(max((int)ix0f, 0), HW - 1);
    int iy0 = min(max((int)iy0f, 0), HW - 1);
    int ix1 = min(ix0 + 1, HW - 1);
    int iy1 = min(iy0 + 1, HW - 1);

    float w00 = (1.0f - wy) * (1.0f - wx);
    float w01 = (1.0f - wy) * wx;
    float w10 = wy * (1.0f - wx);
    float w11 = wy * wx;

    size_t r0 = (size_t)iy0 * HW;
    size_t r1 = (size_t)iy1 * HW;
    size_t o00 = r0 + ix0, o01 = r0 + ix1;
    size_t o10 = r1 + ix0, o11 = r1 + ix1;

    const size_t plane = (size_t)HW * HW;

    float t00[4], t01[4], t10[4], t11[4];
#pragma unroll
    for (int c = 0; c < 4; ++c) {
        const float* p = tex + (size_t)c * plane;
        t00[c] = __ldg(p + o00);
        t01[c] = __ldg(p + o01);
        t10[c] = __ldg(p + o10);
        t11[c] = __ldg(p + o11);
    }
#pragma unroll
    for (int c = 0; c < 4; ++c) {
        float acc = qlevel(t00[c], qmax) * w00
                  + qlevel(t01[c], qmax) * w01
                  + qlevel(t10[c], qmax) * w10
                  + qlevel(t11[c], qmax) * w11;
        res[c] = acc * invq;
    }
}

// ---------------------------------------------------------------- scatter
__global__ void __launch_bounds__(SCBLK)
scatter_kernel(const float* __restrict__ uv) {
    int t = blockIdx.x * SCBLK + threadIdx.x;        // t in [0, NSAMP/4)
    const float4* uv4 = reinterpret_cast<const float4*>(uv);
    float4 a = __ldg(uv4 + 2 * t);
    float4 b = __ldg(uv4 + 2 * t + 1);

    float us[4] = {a.x, a.z, b.x, b.z};
    float vs[4] = {a.y, a.w, b.y, b.w};
    int key[4], pos[4];
#pragma unroll
    for (int k = 0; k < 4; ++k)
        key[k] = sample_key(us[k], vs[k]);
#pragma unroll
    for (int k = 0; k < 4; ++k)                      // 4 independent atomics
        pos[k] = atomicAdd(&g_cursor[key[k]], 1);
#pragma unroll
    for (int k = 0; k < 4; ++k) {
        float4 rec = make_float4(us[k], vs[k],
                                 __int_as_float(4 * t + k), 1.0f);
        if (pos[k] < CAP) {
            g_slots[key[k] * CAP + pos[k]] = rec;
        } else {
            int o = atomicAdd(&g_over_cnt, 1);
            if (o < OCAP) g_over[o] = rec;
        }
    }
}

// ---------------------------------------------------------------- gather
__global__ void __launch_bounds__(BLK)
gather_kernel(const float* __restrict__ hi,
              const float* __restrict__ lo,
              float* __restrict__ out) {
    int b = blockIdx.x;
    int tid = threadIdx.x;
    const size_t plane = (size_t)2048 * 2048;

    if (b < OV_BLOCKS) {
        // ---- cleanup + overflow records (full 16-channel row) ----
        reinterpret_cast<int4*>(g_cursor)[b * BLK + tid] =
            make_int4(0, 0, 0, 0);                 // 16*256 int4 = all bins
        if (b == 0 && tid == 0) g_over_cnt = 0;

        for (int r = b * BLK + tid; r < OCAP; r += OV_BLOCKS * BLK) {
            float4 rec = __ldg(reinterpret_cast<const float4*>(g_over) + r);
            if (rec.w != 0.0f) {
                int idx = __float_as_int(rec.z);
                float res[4];
#pragma unroll
                for (int j = 0; j < 3; ++j) {
                    sample4<2048>(hi + (size_t)(j * 4) * plane, rec.x, rec.y,
                                  255.0f, 1.0f / 255.0f, res);
                    reinterpret_cast<float4*>(out)[(size_t)idx * 4 + j] =
                        make_float4(res[0], res[1], res[2], res[3]);
                }
                sample4<512>(lo, rec.x, rec.y, 15.0f, 1.0f / 15.0f, res);
                reinterpret_cast<float4*>(out)[(size_t)idx * 4 + 3] =
                    make_float4(res[0], res[1], res[2], res[3]);
            }
        }
        return;
    }

    // ---- quad-per-slot gather ----
    int t = (b - OV_BLOCKS) * BLK + tid;
    int s = t >> 2;                                 // slot index
    int j = t & 3;                                  // 0..2 hi group, 3 lo

    float4 rec = __ldg(reinterpret_cast<const float4*>(g_slots) + s);
    if (rec.w == 0.0f) return;                      // empty slot
    int idx = __float_as_int(rec.z);

    float res[4];
    if (j < 3) {
        sample4<2048>(hi + (size_t)(j * 4) * plane, rec.x, rec.y,
                      255.0f, 1.0f / 255.0f, res);
    } else {
        sample4<512>(lo, rec.x, rec.y, 15.0f, 1.0f / 15.0f, res);
    }
    reinterpret_cast<float4*>(out)[(size_t)idx * 4 + j] =
        make_float4(res[0], res[1], res[2], res[3]);
}

// ---------------------------------------------------------------- launch
extern "C" void kernel_launch(void* const* d_in, const int* in_sizes, int n_in,
                              void* d_out, int out_size) {
    const float* uv = (const float*)d_in[0];
    const float* hi = (const float*)d_in[1];
    const float* lo = (const float*)d_in[2];
    float* out = (float*)d_out;

    scatter_kernel<<<NSAMP / 4 / SCBLK, SCBLK>>>(uv);
    gather_kernel<<<GATHER_BLOCKS, BLK>>>(hi, lo, out);
}